// round 8
// baseline (speedup 1.0000x reference)
#include <cuda_runtime.h>
#include <cstdint>

#define DD 4096
#define NSM 148
#define THREADS 1024
#define NW_CONS 28              // consumer warps = rows per block tile
#define PROD_W 28               // producer warp id
#define NCHUNK 16
#define CHUNK 256               // floats per chunk (1KB per row)
#define NBUF 3
#define MATSZ ((size_t)DD * DD)

// smem layout (dynamic):
//   [0, 16384)        s_in (gathered input vector)
//   [16384, 16408)    full mbarriers  (3 x 8B)
//   [16408, 16432)    empty mbarriers (3 x 8B)
//   [17408, ...)      stage ring: NBUF stages of (28KB W [+ 28KB O])
#define SIN_BYTES   16384
#define MBAR_BASE   16384
#define STAGE_BASE  17408
#define ROWCHUNK_B  1024        // CHUNK * 4 bytes
#define WHALF       (NW_CONS * ROWCHUNK_B)   // 28672

__device__ float g_buf0[DD];
__device__ float g_buf1[DD];

__device__ __forceinline__ uint32_t smem_u32(const void* p) {
    return (uint32_t)__cvta_generic_to_shared(p);
}
__device__ __forceinline__ void mbar_init(uint32_t m, uint32_t cnt) {
    asm volatile("mbarrier.init.shared.b64 [%0], %1;" :: "r"(m), "r"(cnt) : "memory");
}
__device__ __forceinline__ void mbar_expect_tx(uint32_t m, uint32_t bytes) {
    asm volatile("mbarrier.arrive.expect_tx.shared.b64 _, [%0], %1;" :: "r"(m), "r"(bytes) : "memory");
}
__device__ __forceinline__ void mbar_arrive(uint32_t m) {
    asm volatile("mbarrier.arrive.shared.b64 _, [%0];" :: "r"(m) : "memory");
}
__device__ __forceinline__ void mbar_wait(uint32_t m, uint32_t parity) {
    asm volatile(
        "{\n\t.reg .pred P;\n"
        "WAITLP_%=:\n\t"
        "mbarrier.try_wait.parity.acquire.cta.shared::cta.b64 P, [%0], %1, 0x989680;\n\t"
        "@!P bra WAITLP_%=;\n\t}"
        :: "r"(m), "r"(parity) : "memory");
}
__device__ __forceinline__ void bulk_g2s(uint32_t dst, const void* src, uint32_t bytes, uint32_t mbar) {
    asm volatile(
        "cp.async.bulk.shared::cta.global.mbarrier::complete_tx::bytes [%0], [%1], %2, [%3];"
        :: "r"(dst), "l"(src), "r"(bytes), "r"(mbar) : "memory");
}

template<bool MASK, bool GATHER, bool SCATTER>
__global__ void __launch_bounds__(THREADS, 1)
gemv_tma(const float* __restrict__ W,
         const float* __restrict__ O,
         const float* __restrict__ bias,
         const float* __restrict__ src,
         const int*   __restrict__ gidx,
         const int*   __restrict__ sidx,
         float*       __restrict__ dst)
{
    extern __shared__ char smem[];
    float* s_in = (float*)smem;
    const uint32_t sbase = smem_u32(smem);

    constexpr uint32_t STRIDE = MASK ? (2 * WHALF) : WHALF;   // stage bytes
    constexpr uint32_t TXB    = STRIDE;                       // expect_tx per stage

    const int t    = threadIdx.x;
    const int lane = t & 31;
    const int w    = t >> 5;

    const int r_start = (int)(((long long)blockIdx.x * DD) / NSM);
    const int r_end   = (int)(((long long)(blockIdx.x + 1) * DD) / NSM);

    auto full_m  = [&](int b) { return sbase + MBAR_BASE + b * 8; };
    auto empty_m = [&](int b) { return sbase + MBAR_BASE + 24 + b * 8; };

    if (t == 0) {
        #pragma unroll
        for (int b = 0; b < NBUF; ++b) {
            mbar_init(full_m(b), 1);
            mbar_init(empty_m(b), NW_CONS);
        }
        asm volatile("fence.proxy.async.shared::cta;" ::: "memory");
    }
    __syncthreads();

    // ---------------- producer: pre-issue first NBUF stages (before gather) ----------------
    const float* wrow = W + (size_t)(r_start + lane) * DD;    // valid: r_start+28 <= 4096
    const float* orow = MASK ? (O + (size_t)(r_start + lane) * DD) : nullptr;
    if (w == PROD_W) {
        #pragma unroll
        for (int s = 0; s < NBUF; ++s) {
            const int b = s;
            if (lane == 0) mbar_expect_tx(full_m(b), TXB);
            if (lane < NW_CONS) {
                const uint32_t d = sbase + STAGE_BASE + b * STRIDE + lane * ROWCHUNK_B;
                bulk_g2s(d, wrow + s * CHUNK, ROWCHUNK_B, full_m(b));
                if (MASK) bulk_g2s(d + WHALF, orow + s * CHUNK, ROWCHUNK_B, full_m(b));
            }
        }
    }

    // ---------------- gather input vector (overlaps the in-flight bulk copies) ----------------
    {
        float tmp[4];
        if (GATHER) {
            int gi[4];
            #pragma unroll
            for (int r = 0; r < 4; ++r) gi[r] = __ldg(gidx + t + r * THREADS);
            #pragma unroll
            for (int r = 0; r < 4; ++r) tmp[r] = __ldcg(src + gi[r]);
        } else {
            #pragma unroll
            for (int r = 0; r < 4; ++r) tmp[r] = __ldg(src + t + r * THREADS);
        }
        #pragma unroll
        for (int r = 0; r < 4; ++r) s_in[t + r * THREADS] = tmp[r];
    }
    __syncthreads();

    if (w == PROD_W) {
        // ---------------- producer main loop ----------------
        for (int s = NBUF; s < NCHUNK; ++s) {
            const int b = s % NBUF;
            mbar_wait(empty_m(b), (uint32_t)((s / NBUF - 1) & 1));
            if (lane == 0) mbar_expect_tx(full_m(b), TXB);
            if (lane < NW_CONS) {
                const uint32_t d = sbase + STAGE_BASE + b * STRIDE + lane * ROWCHUNK_B;
                bulk_g2s(d, wrow + s * CHUNK, ROWCHUNK_B, full_m(b));
                if (MASK) bulk_g2s(d + WHALF, orow + s * CHUNK, ROWCHUNK_B, full_m(b));
            }
        }
        return;
    }
    if (w > PROD_W) return;       // 3 idle warps

    // ---------------- consumers: warp w owns row r_start + w ----------------
    const int row  = r_start + w;
    const bool own = row < r_end;
    const float bv = __ldg(bias + row);
    const int   sc = SCATTER ? __ldg(sidx + row) : row;

    float acc0 = 0.f, acc1 = 0.f;
    #pragma unroll 1
    for (int s = 0; s < NCHUNK; ++s) {
        const int b = s % NBUF;
        mbar_wait(full_m(b), (uint32_t)((s / NBUF) & 1));

        const float4* wr = (const float4*)(smem + STAGE_BASE + b * STRIDE + w * ROWCHUNK_B);
        const float4* xr = (const float4*)(s_in + s * CHUNK);
        const float4 wa = wr[lane],      wb = wr[lane + 32];
        const float4 xa = xr[lane],      xb = xr[lane + 32];
        if (MASK) {
            const float4* orp = (const float4*)(smem + STAGE_BASE + b * STRIDE + WHALF + w * ROWCHUNK_B);
            const float4 oa = orp[lane], ob = orp[lane + 32];
            acc0 = fmaf(wa.x * oa.x, xa.x, acc0);
            acc1 = fmaf(wa.y * oa.y, xa.y, acc1);
            acc0 = fmaf(wa.z * oa.z, xa.z, acc0);
            acc1 = fmaf(wa.w * oa.w, xa.w, acc1);
            acc0 = fmaf(wb.x * ob.x, xb.x, acc0);
            acc1 = fmaf(wb.y * ob.y, xb.y, acc1);
            acc0 = fmaf(wb.z * ob.z, xb.z, acc0);
            acc1 = fmaf(wb.w * ob.w, xb.w, acc1);
        } else {
            acc0 = fmaf(wa.x, xa.x, acc0);
            acc1 = fmaf(wa.y, xa.y, acc1);
            acc0 = fmaf(wa.z, xa.z, acc0);
            acc1 = fmaf(wa.w, xa.w, acc1);
            acc0 = fmaf(wb.x, xb.x, acc0);
            acc1 = fmaf(wb.y, xb.y, acc1);
            acc0 = fmaf(wb.z, xb.z, acc0);
            acc1 = fmaf(wb.w, xb.w, acc1);
        }
        __syncwarp();
        if (lane == 0) mbar_arrive(empty_m(b));
    }

    float acc = acc0 + acc1;
    #pragma unroll
    for (int off = 16; off; off >>= 1) acc += __shfl_down_sync(0xffffffffu, acc, off);
    if (lane == 0 && own) dst[sc] = fmaxf(acc + bv, 0.f);
}

extern "C" void kernel_launch(void* const* d_in, const int* in_sizes, int n_in,
                              void* d_out, int out_size)
{
    const float* x       = (const float*)d_in[0];
    const float* W_in    = (const float*)d_in[1];
    const float* b_in    = (const float*)d_in[2];
    const float* weights = (const float*)d_in[3];
    const float* orders  = (const float*)d_in[4];
    const float* biases  = (const float*)d_in[5];
    const int*   gidx    = (const int*)d_in[6];
    const int*   sidx    = (const int*)d_in[7];
    float*       out     = (float*)d_out;

    float *b0 = nullptr, *b1 = nullptr;
    cudaGetSymbolAddress((void**)&b0, g_buf0);
    cudaGetSymbolAddress((void**)&b1, g_buf1);

    const int SM_MASKED = STAGE_BASE + NBUF * 2 * WHALF;   // 17408 + 3*57344 = 189440
    const int SM_PLAIN  = STAGE_BASE + NBUF * WHALF;       // 17408 + 3*28672 = 103424

    cudaFuncSetAttribute(gemv_tma<false, false, true>,
                         cudaFuncAttributeMaxDynamicSharedMemorySize, SM_PLAIN);
    cudaFuncSetAttribute(gemv_tma<true, true, true>,
                         cudaFuncAttributeMaxDynamicSharedMemorySize, SM_MASKED);
    cudaFuncSetAttribute(gemv_tma<true, true, false>,
                         cudaFuncAttributeMaxDynamicSharedMemorySize, SM_MASKED);

    dim3 grid(NSM), blk(THREADS);

    // input layer
    gemv_tma<false, false, true><<<grid, blk, SM_PLAIN>>>(
        W_in, nullptr, b_in, x, nullptr, sidx, b0);
    // masked layers 0..2
    gemv_tma<true, true, true><<<grid, blk, SM_MASKED>>>(
        weights, orders, biases, b0, gidx, sidx + DD, b1);
    gemv_tma<true, true, true><<<grid, blk, SM_MASKED>>>(
        weights + MATSZ, orders + MATSZ, biases + DD, b1, gidx + DD, sidx + 2 * DD, b0);
    gemv_tma<true, true, true><<<grid, blk, SM_MASKED>>>(
        weights + 2 * MATSZ, orders + 2 * MATSZ, biases + 2 * DD, b0, gidx + 2 * DD, sidx + 3 * DD, b1);
    // final masked layer: pre-scatter output straight to d_out
    gemv_tma<true, true, false><<<grid, blk, SM_MASKED>>>(
        weights + 3 * MATSZ, orders + 3 * MATSZ, biases + 3 * DD, b1, gidx + 3 * DD, nullptr, out);
}

// round 9
// speedup vs baseline: 1.2580x; 1.2580x over previous
#include <cuda_runtime.h>
#include <cstdint>

#define DD 4096
#define NSM 148
#define THREADS 1024
#define NW_CONS 28              // consumer warps = rows per block tile
#define PROD_W 28               // producer warp id
#define NSTAGE 8
#define CHUNKF 512              // floats per stage per row (2KB)
#define NBUF 3
#define MATSZ ((size_t)DD * DD)

#define ROWB        2048                     // CHUNKF * 4
#define STAGEB      (NW_CONS * ROWB)         // 57344
#define MBAR_BASE   16384
#define STAGE_BASE  16448

__device__ float g_buf0[DD];
__device__ float g_buf1[DD];

__device__ __forceinline__ uint32_t smem_u32(const void* p) {
    return (uint32_t)__cvta_generic_to_shared(p);
}
__device__ __forceinline__ void mbar_init(uint32_t m, uint32_t cnt) {
    asm volatile("mbarrier.init.shared.b64 [%0], %1;" :: "r"(m), "r"(cnt) : "memory");
}
__device__ __forceinline__ void mbar_expect_tx(uint32_t m, uint32_t bytes) {
    asm volatile("mbarrier.arrive.expect_tx.shared.b64 _, [%0], %1;" :: "r"(m), "r"(bytes) : "memory");
}
__device__ __forceinline__ void mbar_arrive(uint32_t m) {
    asm volatile("mbarrier.arrive.shared.b64 _, [%0];" :: "r"(m) : "memory");
}
__device__ __forceinline__ void mbar_wait(uint32_t m, uint32_t parity) {
    asm volatile(
        "{\n\t.reg .pred P;\n"
        "WAITLP_%=:\n\t"
        "mbarrier.try_wait.parity.acquire.cta.shared::cta.b64 P, [%0], %1, 0x989680;\n\t"
        "@!P bra WAITLP_%=;\n\t}"
        :: "r"(m), "r"(parity) : "memory");
}
__device__ __forceinline__ void bulk_g2s(uint32_t dst, const void* src, uint32_t bytes, uint32_t mbar) {
    asm volatile(
        "cp.async.bulk.shared::cta.global.mbarrier::complete_tx::bytes [%0], [%1], %2, [%3];"
        :: "r"(dst), "l"(src), "r"(bytes), "r"(mbar) : "memory");
}

// ---------------- masked layers: W via LDG (double-buffered), O via cp.async.bulk -> smem ----------
template<bool SCATTER>
__global__ void __launch_bounds__(THREADS, 1)
gemv_split(const float* __restrict__ W,
           const float* __restrict__ O,
           const float* __restrict__ bias,
           const float* __restrict__ src,
           const int*   __restrict__ gidx,
           const int*   __restrict__ sidx,
           float*       __restrict__ dst)
{
    extern __shared__ char smem[];
    float* s_in = (float*)smem;
    const uint32_t sbase = smem_u32(smem);

    const int t    = threadIdx.x;
    const int lane = t & 31;
    const int w    = t >> 5;

    const int r_start = (int)(((long long)blockIdx.x * DD) / NSM);
    const int r_end   = (int)(((long long)(blockIdx.x + 1) * DD) / NSM);

    auto full_m  = [&](int b) { return sbase + MBAR_BASE + b * 8; };
    auto empty_m = [&](int b) { return sbase + MBAR_BASE + 24 + b * 8; };

    if (t == 0) {
        #pragma unroll
        for (int b = 0; b < NBUF; ++b) {
            mbar_init(full_m(b), 1);
            mbar_init(empty_m(b), NW_CONS);
        }
        asm volatile("fence.proxy.async.shared::cta;" ::: "memory");
    }
    __syncthreads();

    // producer: pre-issue first NBUF O stages (in flight during the gather below)
    if (w == PROD_W) {
        const int rowp = min(r_start + lane, DD - 1);
        const float* orow = O + (size_t)rowp * DD;
        #pragma unroll
        for (int s = 0; s < NBUF; ++s) {
            if (lane == 0) mbar_expect_tx(full_m(s), STAGEB);
            if (lane < NW_CONS)
                bulk_g2s(sbase + STAGE_BASE + s * STAGEB + lane * ROWB,
                         orow + s * CHUNKF, ROWB, full_m(s));
        }
    }

    // consumers: preload W stage 0 into registers (also overlaps the gather)
    const int row = min(r_start + w, DD - 1);       // clamp: warp 27 of 27-row blocks duplicates
    const bool own = (r_start + w) < r_end;
    const float4* __restrict__ w4 = reinterpret_cast<const float4*>(W + (size_t)row * DD) + lane;
    float4 wb[4];
    if (w < NW_CONS) {
        #pragma unroll
        for (int u = 0; u < 4; ++u) wb[u] = __ldcs(w4 + u * 32);
    }

    // gather input vector into smem (4 independent scattered loads per thread)
    {
        int gi[4];
        #pragma unroll
        for (int r = 0; r < 4; ++r) gi[r] = __ldg(gidx + t + r * THREADS);
        float tmp[4];
        #pragma unroll
        for (int r = 0; r < 4; ++r) tmp[r] = __ldcg(src + gi[r]);
        #pragma unroll
        for (int r = 0; r < 4; ++r) s_in[t + r * THREADS] = tmp[r];
    }
    __syncthreads();

    if (w == PROD_W) {
        const int rowp = min(r_start + lane, DD - 1);
        const float* orow = O + (size_t)rowp * DD;
        #pragma unroll
        for (int s = NBUF; s < NSTAGE; ++s) {
            const int b = s % NBUF;
            mbar_wait(empty_m(b), (uint32_t)((s / NBUF - 1) & 1));
            if (lane == 0) mbar_expect_tx(full_m(b), STAGEB);
            if (lane < NW_CONS)
                bulk_g2s(sbase + STAGE_BASE + b * STAGEB + lane * ROWB,
                         orow + s * CHUNKF, ROWB, full_m(b));
        }
        return;
    }
    if (w > PROD_W) return;

    // consumer main loop: 8 stages, W prefetched one stage ahead in registers
    float acc0 = 0.f, acc1 = 0.f;
    const uint32_t omy = STAGE_BASE + w * ROWB;

    #pragma unroll
    for (int s = 0; s < NSTAGE; ++s) {
        const int b = s % NBUF;
        float4 wn[4];
        if (s < NSTAGE - 1) {
            #pragma unroll
            for (int u = 0; u < 4; ++u) wn[u] = __ldcs(w4 + (s + 1) * 128 + u * 32);
        }
        mbar_wait(full_m(b), (uint32_t)((s / NBUF) & 1));

        const float4* __restrict__ op = reinterpret_cast<const float4*>(smem + omy + b * STAGEB) + lane;
        const float4* __restrict__ xp = reinterpret_cast<const float4*>(s_in + s * CHUNKF) + lane;
        #pragma unroll
        for (int u = 0; u < 4; ++u) {
            const float4 o  = op[u * 32];
            const float4 xv = xp[u * 32];
            acc0 = fmaf(wb[u].x * o.x, xv.x, acc0);
            acc1 = fmaf(wb[u].y * o.y, xv.y, acc1);
            acc0 = fmaf(wb[u].z * o.z, xv.z, acc0);
            acc1 = fmaf(wb[u].w * o.w, xv.w, acc1);
        }
        __syncwarp();
        if (lane == 0) mbar_arrive(empty_m(b));
        if (s < NSTAGE - 1) {
            #pragma unroll
            for (int u = 0; u < 4; ++u) wb[u] = wn[u];
        }
    }

    float acc = acc0 + acc1;
    #pragma unroll
    for (int off = 16; off; off >>= 1) acc += __shfl_down_sync(0xffffffffu, acc, off);
    if (lane == 0 && own) {
        float v = fmaxf(acc + __ldg(bias + row), 0.f);
        if (SCATTER) dst[__ldg(sidx + row)] = v;
        else         dst[row] = v;
    }
}

// ---------------- input layer: R3's proven pure-LDG form ----------------
__global__ void __launch_bounds__(THREADS, 1)
gemv_plain(const float* __restrict__ W,
           const float* __restrict__ bias,
           const float* __restrict__ src,
           const int*   __restrict__ sidx,
           float* __restrict__ dst)
{
    __shared__ float s_in[DD];
    const int t = threadIdx.x;
    #pragma unroll
    for (int j = t; j < DD; j += THREADS) s_in[j] = __ldg(src + j);
    __syncthreads();

    const int r_start = (int)(((long long)blockIdx.x * DD) / NSM);
    const int r_end   = (int)(((long long)(blockIdx.x + 1) * DD) / NSM);
    const int lane = t & 31;
    const int row  = r_start + (t >> 5);
    if (row >= r_end) return;

    const float4* __restrict__ w4 = reinterpret_cast<const float4*>(W + (size_t)row * DD) + lane;
    const float4* __restrict__ s4 = reinterpret_cast<const float4*>(s_in) + lane;
    float acc0 = 0.f, acc1 = 0.f;
    float4 wb[8];
    #pragma unroll
    for (int base = 0; base < 32; base += 8) {
        #pragma unroll
        for (int u = 0; u < 8; ++u) wb[u] = __ldcs(w4 + (base + u) * 32);
        #pragma unroll
        for (int u = 0; u < 8; ++u) {
            const float4 xi = s4[(base + u) * 32];
            acc0 = fmaf(wb[u].x, xi.x, acc0);
            acc1 = fmaf(wb[u].y, xi.y, acc1);
            acc0 = fmaf(wb[u].z, xi.z, acc0);
            acc1 = fmaf(wb[u].w, xi.w, acc1);
        }
    }
    float acc = acc0 + acc1;
    #pragma unroll
    for (int off = 16; off; off >>= 1) acc += __shfl_down_sync(0xffffffffu, acc, off);
    if (lane == 0) dst[__ldg(sidx + row)] = fmaxf(acc + __ldg(bias + row), 0.f);
}

extern "C" void kernel_launch(void* const* d_in, const int* in_sizes, int n_in,
                              void* d_out, int out_size)
{
    const float* x       = (const float*)d_in[0];
    const float* W_in    = (const float*)d_in[1];
    const float* b_in    = (const float*)d_in[2];
    const float* weights = (const float*)d_in[3];
    const float* orders  = (const float*)d_in[4];
    const float* biases  = (const float*)d_in[5];
    const int*   gidx    = (const int*)d_in[6];
    const int*   sidx    = (const int*)d_in[7];
    float*       out     = (float*)d_out;

    float *b0 = nullptr, *b1 = nullptr;
    cudaGetSymbolAddress((void**)&b0, g_buf0);
    cudaGetSymbolAddress((void**)&b1, g_buf1);

    const int SMEM = STAGE_BASE + NBUF * STAGEB;   // 16448 + 172032 = 188480
    cudaFuncSetAttribute(gemv_split<true>,
                         cudaFuncAttributeMaxDynamicSharedMemorySize, SMEM);
    cudaFuncSetAttribute(gemv_split<false>,
                         cudaFuncAttributeMaxDynamicSharedMemorySize, SMEM);

    dim3 grid(NSM), blk(THREADS);

    gemv_plain<<<grid, blk>>>(W_in, b_in, x, sidx, b0);

    gemv_split<true><<<grid, blk, SMEM>>>(
        weights, orders, biases, b0, gidx, sidx + DD, b1);
    gemv_split<true><<<grid, blk, SMEM>>>(
        weights + MATSZ, orders + MATSZ, biases + DD, b1, gidx + DD, sidx + 2 * DD, b0);
    gemv_split<true><<<grid, blk, SMEM>>>(
        weights + 2 * MATSZ, orders + 2 * MATSZ, biases + 2 * DD, b0, gidx + 2 * DD, sidx + 3 * DD, b1);
    gemv_split<false><<<grid, blk, SMEM>>>(
        weights + 3 * MATSZ, orders + 3 * MATSZ, biases + 3 * DD, b1, gidx + 3 * DD, nullptr, out);
}